// round 7
// baseline (speedup 1.0000x reference)
#include <cuda_runtime.h>
#include <cuda_bf16.h>
#include <math.h>

// Swin-style window cross-attention.
// B=128, N=256 (16x16 window), C=512, H=8, d=64.

// Scratch (device globals; 258 MB total — no allocation anywhere).
__device__ float g_qlin [32768LL * 512];   // [B*N, C]      64 MB
__device__ float g_kvlin[32768LL * 1024];  // [B*N, 2C]    128 MB
__device__ float g_o    [32768LL * 512];   // [B,N,C]       64 MB (head-interleaved)
__device__ float g_bias [8LL * 256 * 256]; // [H,N,N]        2 MB

// ---------------------------------------------------------------------------
// fp32 tiled GEMM body: C[M,N] = A[M,K] @ B[K,N] (+ optional col bias).
// 128x128 tile, BK=8, 8x8 per thread, 256 threads.
// ---------------------------------------------------------------------------
template<int EPI, int M, int N, int K, int LDA, int LDB, int LDC>
__device__ __forceinline__ void
sgemm_body(const float* __restrict__ A, const float* __restrict__ Bm,
           float* __restrict__ C, const float* __restrict__ bias)
{
    constexpr int BM = 128, BN = 128, BK = 8, TM = 8, TN = 8;
    constexpr int THREADS = (BM/TM)*(BN/TN);   // 256

    __shared__ float As[BK][BM];
    __shared__ float Bs[BK][BN];

    const int tid  = threadIdx.x;
    const int tx   = tid % (BN/TN);
    const int ty   = tid / (BN/TN);
    const int row0 = blockIdx.y * BM;
    const int col0 = blockIdx.x * BN;

    float acc[TM][TN];
    #pragma unroll
    for (int i = 0; i < TM; i++)
        #pragma unroll
        for (int j = 0; j < TN; j++) acc[i][j] = 0.0f;

    for (int k0 = 0; k0 < K; k0 += BK) {
        // A tile (BM x BK) -> As[k][m] transposed
        #pragma unroll
        for (int q = tid; q < BM*BK/4; q += THREADS) {
            int r  = q / (BK/4);
            int kk = (q % (BK/4)) * 4;
            float4 v = *(const float4*)(A + (long long)(row0 + r)*LDA + k0 + kk);
            As[kk+0][r] = v.x; As[kk+1][r] = v.y;
            As[kk+2][r] = v.z; As[kk+3][r] = v.w;
        }
        // B tile -> Bs[k][n]
        #pragma unroll
        for (int q = tid; q < BK*BN/4; q += THREADS) {
            int kr = q / (BN/4);
            int nn = (q % (BN/4)) * 4;
            *(float4*)&Bs[kr][nn] =
                *(const float4*)(Bm + (long long)(k0 + kr)*LDB + col0 + nn);
        }
        __syncthreads();

        #pragma unroll
        for (int k = 0; k < BK; k++) {
            float a[TM], b[TN];
            #pragma unroll
            for (int i = 0; i < TM; i += 4) {
                float4 v = *(const float4*)&As[k][ty*TM + i];
                a[i+0] = v.x; a[i+1] = v.y; a[i+2] = v.z; a[i+3] = v.w;
            }
            #pragma unroll
            for (int j = 0; j < TN; j += 4) {
                float4 v = *(const float4*)&Bs[k][tx*TN + j];
                b[j+0] = v.x; b[j+1] = v.y; b[j+2] = v.z; b[j+3] = v.w;
            }
            #pragma unroll
            for (int i = 0; i < TM; i++)
                #pragma unroll
                for (int j = 0; j < TN; j++)
                    acc[i][j] += a[i] * b[j];
        }
        __syncthreads();
    }

    #pragma unroll
    for (int i = 0; i < TM; i++) {
        int r = row0 + ty*TM + i;
        #pragma unroll
        for (int j = 0; j < TN; j += 4) {
            int c = col0 + tx*TN + j;
            float4 o;
            o.x = acc[i][j+0]; o.y = acc[i][j+1];
            o.z = acc[i][j+2]; o.w = acc[i][j+3];
            if (EPI == 1) {
                float4 bv = *(const float4*)(bias + c);
                o.x += bv.x; o.y += bv.y; o.z += bv.z; o.w += bv.w;
            }
            *(float4*)(C + (long long)r*LDC + c) = o;
        }
    }
}

// 1) q_lin = x @ q_w   [32768,512]
__global__ void __launch_bounds__(256)
k_gemm_q(const float* __restrict__ x, const float* __restrict__ q_w)
{
    sgemm_body<0, 32768,512,512, 512,512,512>(x, q_w, g_qlin, nullptr);
}

// 2) kv_lin = y @ kv_w  [32768,1024]
__global__ void __launch_bounds__(256)
k_gemm_kv(const float* __restrict__ y, const float* __restrict__ kv_w)
{
    sgemm_body<0, 32768,1024,512, 512,1024,1024>(y, kv_w, g_kvlin, nullptr);
}

// 4) out = o @ proj_w + proj_b  [32768,512]
__global__ void __launch_bounds__(256)
k_gemm_proj(const float* __restrict__ proj_w, const float* __restrict__ proj_b,
            float* __restrict__ out)
{
    sgemm_body<1, 32768,512,512, 512,512,512>(g_o, proj_w, out, proj_b);
}

// ---------------------------------------------------------------------------
// 3) Fused attention: per CTA = (q-tile of 64, head, batch).
//    S = 0.125 * Q K^T + bias  -> exact softmax (full 256-wide row in smem)
//    O = P V, written head-interleaved into g_o.
//    smem: QT[64][64] (16KB) | KV[64][64] (16KB, K then V) | S[64][256] (64KB)
// ---------------------------------------------------------------------------
__global__ void __launch_bounds__(256)
k_attn_fused()
{
    extern __shared__ float sm[];
    float* sQT = sm;            // [dd][qi]   64*64
    float* sKV = sm + 4096;     // [dd][kj] for K phase, [k][dd] for V phase
    float* sS  = sm + 8192;     // [qi][k]    64*256

    const int tid = threadIdx.x;
    const int tx  = tid & 15;         // 0..15
    const int ty  = tid >> 4;         // 0..15
    const int qt  = blockIdx.x;       // 0..3
    const int h   = blockIdx.y;       // 0..7
    const int b   = blockIdx.z;       // 0..127

    const long long qbase = (long long)b*131072 + (long long)(qt*64)*512 + h*64;
    const long long kvb   = (long long)b*262144 + h*64;

    // ---- load Q tile transposed: sQT[c][r] = Q[r][c]
    // mapping: r fast over warp -> conflict-free smem stores
    #pragma unroll
    for (int q = tid; q < 1024; q += 256) {
        int r  = q & 63;
        int c4 = (q >> 6) * 4;
        float4 v = *(const float4*)(g_qlin + qbase + (long long)r*512 + c4);
        sQT[(c4+0)*64 + r] = v.x;
        sQT[(c4+1)*64 + r] = v.y;
        sQT[(c4+2)*64 + r] = v.z;
        sQT[(c4+3)*64 + r] = v.w;
    }

    // ================= Phase 1: S = 0.125*Q@K^T + bias =================
    for (int kt = 0; kt < 4; kt++) {
        __syncthreads();   // sQT ready (1st iter) / sKV free (later iters)
        // load K tile transposed: sKV[c][kj] = K[kt*64+kj][c]
        const long long kbase = kvb + (long long)(kt*64)*1024;
        #pragma unroll
        for (int q = tid; q < 1024; q += 256) {
            int r  = q & 63;
            int c4 = (q >> 6) * 4;
            float4 v = *(const float4*)(g_kvlin + kbase + (long long)r*1024 + c4);
            sKV[(c4+0)*64 + r] = v.x;
            sKV[(c4+1)*64 + r] = v.y;
            sKV[(c4+2)*64 + r] = v.z;
            sKV[(c4+3)*64 + r] = v.w;
        }
        __syncthreads();

        float acc[4][4];
        #pragma unroll
        for (int i = 0; i < 4; i++)
            #pragma unroll
            for (int j = 0; j < 4; j++) acc[i][j] = 0.0f;

        #pragma unroll 8
        for (int kk = 0; kk < 64; kk++) {
            float4 av = *(const float4*)&sQT[kk*64 + ty*4];
            float4 bv = *(const float4*)&sKV[kk*64 + tx*4];
            float a[4] = {av.x, av.y, av.z, av.w};
            float bb[4] = {bv.x, bv.y, bv.z, bv.w};
            #pragma unroll
            for (int i = 0; i < 4; i++)
                #pragma unroll
                for (int j = 0; j < 4; j++)
                    acc[i][j] += a[i] * bb[j];
        }

        // scale + relative-position bias, write into sS
        const int qg = qt*64 + ty*4;
        const float* brow = g_bias + (long long)h*65536;
        #pragma unroll
        for (int i = 0; i < 4; i++) {
            float4 bv = *(const float4*)&brow[(long long)(qg+i)*256 + kt*64 + tx*4];
            float4 o;
            o.x = acc[i][0]*0.125f + bv.x;
            o.y = acc[i][1]*0.125f + bv.y;
            o.z = acc[i][2]*0.125f + bv.z;
            o.w = acc[i][3]*0.125f + bv.w;
            *(float4*)&sS[(ty*4+i)*256 + kt*64 + tx*4] = o;
        }
    }
    __syncthreads();

    // ================= Phase 2: exact softmax over 256-wide rows =======
    {
        const int wid  = tid >> 5;
        const int lane = tid & 31;
        #pragma unroll
        for (int rr = 0; rr < 8; rr++) {
            float* p = sS + (wid*8 + rr)*256;
            float v[8];
            float mx = -1e30f;
            #pragma unroll
            for (int i = 0; i < 8; i++) {
                v[i] = p[lane + 32*i];
                mx = fmaxf(mx, v[i]);
            }
            #pragma unroll
            for (int off = 16; off > 0; off >>= 1)
                mx = fmaxf(mx, __shfl_xor_sync(0xffffffffu, mx, off));
            float s = 0.0f;
            #pragma unroll
            for (int i = 0; i < 8; i++) {
                v[i] = __expf(v[i] - mx);
                s += v[i];
            }
            #pragma unroll
            for (int off = 16; off > 0; off >>= 1)
                s += __shfl_xor_sync(0xffffffffu, s, off);
            float inv = 1.0f / s;
            #pragma unroll
            for (int i = 0; i < 8; i++)
                p[lane + 32*i] = v[i] * inv;
        }
    }
    __syncthreads();

    // ================= Phase 3: O = P @ V ==============================
    float oacc[4][4];
    #pragma unroll
    for (int i = 0; i < 4; i++)
        #pragma unroll
        for (int j = 0; j < 4; j++) oacc[i][j] = 0.0f;

    for (int kt = 0; kt < 4; kt++) {
        // load V tile row-major: sKV[k][dd]
        const long long vbase = kvb + (long long)(kt*64)*1024 + 512;
        #pragma unroll
        for (int q = tid; q < 1024; q += 256) {
            int r  = q >> 4;
            int c4 = (q & 15) * 4;
            *(float4*)&sKV[r*64 + c4] =
                *(const float4*)(g_kvlin + vbase + (long long)r*1024 + c4);
        }
        __syncthreads();

        #pragma unroll 8
        for (int kl = 0; kl < 64; kl++) {
            float4 bv = *(const float4*)&sKV[kl*64 + tx*4];
            float bb[4] = {bv.x, bv.y, bv.z, bv.w};
            float a[4];
            #pragma unroll
            for (int i = 0; i < 4; i++)
                a[i] = sS[(ty*4+i)*256 + kt*64 + kl];
            #pragma unroll
            for (int i = 0; i < 4; i++)
                #pragma unroll
                for (int j = 0; j < 4; j++)
                    oacc[i][j] += a[i] * bb[j];
        }
        __syncthreads();
    }

    // write O head-interleaved: g_o[b, qt*64+qi, h*64+dd]
    const long long obase = (long long)b*131072 + (long long)(qt*64)*512 + h*64;
    #pragma unroll
    for (int i = 0; i < 4; i++) {
        float4 o;
        o.x = oacc[i][0]; o.y = oacc[i][1];
        o.z = oacc[i][2]; o.w = oacc[i][3];
        *(float4*)(g_o + obase + (long long)(ty*4+i)*512 + tx*4) = o;
    }
}

// ---------------------------------------------------------------------------
// Relative-position bias matrix g_bias[h][i][j] from bias_table [961,8].
// ---------------------------------------------------------------------------
__global__ void __launch_bounds__(256)
k_build_bias(const float* __restrict__ table)
{
    int t = blockIdx.x * blockDim.x + threadIdx.x;   // 65536 = 256*256
    int i = t >> 8, j = t & 255;
    int dh = (i >> 4) - (j >> 4) + 15;
    int dw = (i & 15) - (j & 15) + 15;
    int idx = dh * 31 + dw;                          // 2*16-1 = 31
    #pragma unroll
    for (int h = 0; h < 8; h++)
        g_bias[(long long)h * 65536 + t] = table[idx * 8 + h];
}

// ---------------------------------------------------------------------------
extern "C" void kernel_launch(void* const* d_in, const int* in_sizes, int n_in,
                              void* d_out, int out_size)
{
    const float* x      = (const float*)d_in[0];  // [128,256,512]
    const float* y      = (const float*)d_in[1];  // [128,256,512]
    const float* q_w    = (const float*)d_in[2];  // [512,512]
    const float* kv_w   = (const float*)d_in[3];  // [512,1024]
    const float* proj_w = (const float*)d_in[4];  // [512,512]
    const float* proj_b = (const float*)d_in[5];  // [512]
    const float* table  = (const float*)d_in[6];  // [961,8]
    float* out = (float*)d_out;

    // 96 KB dynamic smem opt-in for the fused attention kernel
    // (host-side attribute; not a stream op — graph-capture safe).
    cudaFuncSetAttribute(k_attn_fused,
                         cudaFuncAttributeMaxDynamicSharedMemorySize, 98304);

    k_build_bias<<<256, 256>>>(table);

    k_gemm_q <<<dim3(512/128,  32768/128, 1), 256>>>(x, q_w);
    k_gemm_kv<<<dim3(1024/128, 32768/128, 1), 256>>>(y, kv_w);

    k_attn_fused<<<dim3(4, 8, 128), 256, 98304>>>();

    k_gemm_proj<<<dim3(512/128, 32768/128, 1), 256>>>(proj_w, proj_b, out);
}

// round 8
// speedup vs baseline: 2.0123x; 2.0123x over previous
#include <cuda_runtime.h>
#include <cuda_bf16.h>
#include <math.h>
#include <stdint.h>

// Swin-style window cross-attention.
// B=128, N=256 (16x16 window), C=512, H=8, d=64.

// Scratch (device globals; no allocation anywhere).
__device__ float g_qlin [32768LL * 512];   // [B*N, C]      64 MB
__device__ float g_kvlin[32768LL * 1024];  // [B*N, 2C]    128 MB
__device__ float g_o    [32768LL * 512];   // [B,N,C]       64 MB (head-interleaved)
__device__ float g_bias [8LL * 256 * 256]; // [H,N,N]        2 MB

// ---------------------------------------------------------------------------
// Helpers
// ---------------------------------------------------------------------------
__device__ __forceinline__ uint32_t smem_u32(const void* p) {
    return (uint32_t)__cvta_generic_to_shared(p);
}
__device__ __forceinline__ uint32_t pack_bf2(float a, float b) {
    __nv_bfloat162 t = __floats2bfloat162_rn(a, b);
    return *reinterpret_cast<uint32_t*>(&t);
}
__device__ __forceinline__ void ldm_x4(uint32_t* r, uint32_t addr) {
    asm volatile("ldmatrix.sync.aligned.m8n8.x4.shared.b16 {%0,%1,%2,%3}, [%4];"
                 : "=r"(r[0]), "=r"(r[1]), "=r"(r[2]), "=r"(r[3]) : "r"(addr));
}
__device__ __forceinline__ void ldm_x4_t(uint32_t* r, uint32_t addr) {
    asm volatile("ldmatrix.sync.aligned.m8n8.x4.trans.shared.b16 {%0,%1,%2,%3}, [%4];"
                 : "=r"(r[0]), "=r"(r[1]), "=r"(r[2]), "=r"(r[3]) : "r"(addr));
}
__device__ __forceinline__ void mma_bf16(float* c, const uint32_t* a, const uint32_t* b) {
    asm volatile(
        "mma.sync.aligned.m16n8k16.row.col.f32.bf16.bf16.f32 "
        "{%0,%1,%2,%3}, {%4,%5,%6,%7}, {%8,%9}, {%0,%1,%2,%3};"
        : "+f"(c[0]), "+f"(c[1]), "+f"(c[2]), "+f"(c[3])
        : "r"(a[0]), "r"(a[1]), "r"(a[2]), "r"(a[3]), "r"(b[0]), "r"(b[1]));
}

// ---------------------------------------------------------------------------
// Split-bf16 tensor-core GEMM: C[M,N] = A[M,K] @ B[K,N] (+ optional col bias).
// A,B,C fp32 row-major. 3-term split: hi*hi + hi*lo + lo*hi (lo*lo dropped,
// error ~2^-16 relative).
// CTA tile 128x128, BK=32, 256 threads, 8 warps as 4(m) x 2(n): warp 32x64.
// ---------------------------------------------------------------------------
template<int EPI, int M, int N, int K, int LDA, int LDB, int LDC>
__device__ __forceinline__ void
mma_gemm_body(const float* __restrict__ A, const float* __restrict__ Bm,
              float* __restrict__ C, const float* __restrict__ bias)
{
    constexpr int BK  = 32;
    constexpr int PA  = 40;   // A smem pitch (elems): 80B rows -> conflict-free ldmatrix
    constexpr int PB  = 136;  // B smem pitch (elems): 272B rows -> conflict-free ldmatrix

    __shared__ __nv_bfloat16 sAh[128 * PA];
    __shared__ __nv_bfloat16 sAl[128 * PA];
    __shared__ __nv_bfloat16 sBh[BK * PB];
    __shared__ __nv_bfloat16 sBl[BK * PB];

    const int tid  = threadIdx.x;
    const int wid  = tid >> 5;
    const int lane = tid & 31;
    const int wm   = wid >> 1;     // 0..3  -> warp rows = wm*32
    const int wn   = wid & 1;      // 0..1  -> warp cols = wn*64
    const int row0 = blockIdx.y * 128;
    const int col0 = blockIdx.x * 128;

    float acc[2][8][4];
    #pragma unroll
    for (int i = 0; i < 2; i++)
        #pragma unroll
        for (int j = 0; j < 8; j++)
            #pragma unroll
            for (int q = 0; q < 4; q++) acc[i][j][q] = 0.0f;

    // gmem->smem mapping
    const int ar  = tid >> 3;          // 0..31 (A row block, step 32)
    const int ac4 = (tid & 7) * 4;     // A col
    const int br  = tid >> 5;          // 0..7  (B row, step 8)
    const int bc4 = (tid & 31) * 4;    // B col

    for (int k0 = 0; k0 < K; k0 += BK) {
        // ---- A chunk [128 x 32]: split into hi/lo bf16
        #pragma unroll
        for (int i = 0; i < 4; i++) {
            int r = ar + i * 32;
            float4 v = *(const float4*)(A + (long long)(row0 + r) * LDA + k0 + ac4);
            float h0 = __bfloat162float(__float2bfloat16_rn(v.x));
            float h1 = __bfloat162float(__float2bfloat16_rn(v.y));
            float h2 = __bfloat162float(__float2bfloat16_rn(v.z));
            float h3 = __bfloat162float(__float2bfloat16_rn(v.w));
            uint2 ph = { pack_bf2(h0, h1), pack_bf2(h2, h3) };
            uint2 pl = { pack_bf2(v.x - h0, v.y - h1), pack_bf2(v.z - h2, v.w - h3) };
            *(uint2*)&sAh[r * PA + ac4] = ph;
            *(uint2*)&sAl[r * PA + ac4] = pl;
        }
        // ---- B chunk [32 x 128]
        #pragma unroll
        for (int i = 0; i < 4; i++) {
            int r = br + i * 8;
            float4 v = *(const float4*)(Bm + (long long)(k0 + r) * LDB + col0 + bc4);
            float h0 = __bfloat162float(__float2bfloat16_rn(v.x));
            float h1 = __bfloat162float(__float2bfloat16_rn(v.y));
            float h2 = __bfloat162float(__float2bfloat16_rn(v.z));
            float h3 = __bfloat162float(__float2bfloat16_rn(v.w));
            uint2 ph = { pack_bf2(h0, h1), pack_bf2(h2, h3) };
            uint2 pl = { pack_bf2(v.x - h0, v.y - h1), pack_bf2(v.z - h2, v.w - h3) };
            *(uint2*)&sBh[r * PB + bc4] = ph;
            *(uint2*)&sBl[r * PB + bc4] = pl;
        }
        __syncthreads();

        #pragma unroll
        for (int ks = 0; ks < 2; ks++) {
            // fragment smem offsets
            const int arow = wm * 32 + (lane & 15);
            const int acol = ks * 16 + ((lane >> 4) << 3);
            const int brow = ks * 16 + (lane & 15);

            uint32_t ah[2][4], al[2][4], bb[8][2];

            // A-hi frags
            #pragma unroll
            for (int mf = 0; mf < 2; mf++)
                ldm_x4(ah[mf], smem_u32(&sAh[(arow + mf * 16) * PA + acol]));
            // B-hi frags (4x ldmatrix.x4.trans, each covers two n-frags)
            #pragma unroll
            for (int np = 0; np < 4; np++) {
                uint32_t r[4];
                int bcol = wn * 64 + np * 16 + ((lane >> 4) << 3);
                ldm_x4_t(r, smem_u32(&sBh[brow * PB + bcol]));
                bb[2*np][0] = r[0]; bb[2*np][1] = r[1];
                bb[2*np+1][0] = r[2]; bb[2*np+1][1] = r[3];
            }
            // hi * hi
            #pragma unroll
            for (int mf = 0; mf < 2; mf++)
                #pragma unroll
                for (int nf = 0; nf < 8; nf++)
                    mma_bf16(acc[mf][nf], ah[mf], bb[nf]);

            // A-lo frags; lo * hi
            #pragma unroll
            for (int mf = 0; mf < 2; mf++)
                ldm_x4(al[mf], smem_u32(&sAl[(arow + mf * 16) * PA + acol]));
            #pragma unroll
            for (int mf = 0; mf < 2; mf++)
                #pragma unroll
                for (int nf = 0; nf < 8; nf++)
                    mma_bf16(acc[mf][nf], al[mf], bb[nf]);

            // B-lo frags (reuse bb regs); hi * lo
            #pragma unroll
            for (int np = 0; np < 4; np++) {
                uint32_t r[4];
                int bcol = wn * 64 + np * 16 + ((lane >> 4) << 3);
                ldm_x4_t(r, smem_u32(&sBl[brow * PB + bcol]));
                bb[2*np][0] = r[0]; bb[2*np][1] = r[1];
                bb[2*np+1][0] = r[2]; bb[2*np+1][1] = r[3];
            }
            #pragma unroll
            for (int mf = 0; mf < 2; mf++)
                #pragma unroll
                for (int nf = 0; nf < 8; nf++)
                    mma_bf16(acc[mf][nf], ah[mf], bb[nf]);
        }
        __syncthreads();
    }

    // ---- epilogue
    #pragma unroll
    for (int mf = 0; mf < 2; mf++) {
        #pragma unroll
        for (int nf = 0; nf < 8; nf++) {
            int r = row0 + wm * 32 + mf * 16 + (lane >> 2);
            int c = col0 + wn * 64 + nf * 8 + (lane & 3) * 2;
            float2 v0 = { acc[mf][nf][0], acc[mf][nf][1] };
            float2 v1 = { acc[mf][nf][2], acc[mf][nf][3] };
            if (EPI == 1) {
                v0.x += bias[c]; v0.y += bias[c + 1];
                v1.x += bias[c]; v1.y += bias[c + 1];
            }
            *(float2*)(C + (long long)r * LDC + c)       = v0;
            *(float2*)(C + (long long)(r + 8) * LDC + c) = v1;
        }
    }
}

// 1) q_lin = x @ q_w   [32768,512]
__global__ void __launch_bounds__(256)
k_gemm_q(const float* __restrict__ x, const float* __restrict__ q_w)
{
    mma_gemm_body<0, 32768,512,512, 512,512,512>(x, q_w, g_qlin, nullptr);
}

// 2) kv_lin = y @ kv_w  [32768,1024]
__global__ void __launch_bounds__(256)
k_gemm_kv(const float* __restrict__ y, const float* __restrict__ kv_w)
{
    mma_gemm_body<0, 32768,1024,512, 512,1024,1024>(y, kv_w, g_kvlin, nullptr);
}

// 4) out = o @ proj_w + proj_b  [32768,512]
__global__ void __launch_bounds__(256)
k_gemm_proj(const float* __restrict__ proj_w, const float* __restrict__ proj_b,
            float* __restrict__ out)
{
    mma_gemm_body<1, 32768,512,512, 512,512,512>(g_o, proj_w, out, proj_b);
}

// ---------------------------------------------------------------------------
// 3) Fused attention: per CTA = (q-tile of 64, head, batch). fp32.
//    S = 0.125 * Q K^T + bias -> exact softmax (256-wide row in smem) -> O = P V
//    smem: QT[64][64] | KV[64][64] | S[64][256]  = 96 KB
// ---------------------------------------------------------------------------
__global__ void __launch_bounds__(256)
k_attn_fused()
{
    extern __shared__ float sm[];
    float* sQT = sm;            // [dd][qi]
    float* sKV = sm + 4096;     // [dd][kj] (K phase) / [k][dd] (V phase)
    float* sS  = sm + 8192;     // [qi][k]

    const int tid = threadIdx.x;
    const int tx  = tid & 15;
    const int ty  = tid >> 4;
    const int qt  = blockIdx.x;
    const int h   = blockIdx.y;
    const int b   = blockIdx.z;

    const long long qbase = (long long)b*131072 + (long long)(qt*64)*512 + h*64;
    const long long kvb   = (long long)b*262144 + h*64;

    #pragma unroll
    for (int q = tid; q < 1024; q += 256) {
        int r  = q & 63;
        int c4 = (q >> 6) * 4;
        float4 v = *(const float4*)(g_qlin + qbase + (long long)r*512 + c4);
        sQT[(c4+0)*64 + r] = v.x;
        sQT[(c4+1)*64 + r] = v.y;
        sQT[(c4+2)*64 + r] = v.z;
        sQT[(c4+3)*64 + r] = v.w;
    }

    // Phase 1: S = 0.125*Q@K^T + bias
    for (int kt = 0; kt < 4; kt++) {
        __syncthreads();
        const long long kbase = kvb + (long long)(kt*64)*1024;
        #pragma unroll
        for (int q = tid; q < 1024; q += 256) {
            int r  = q & 63;
            int c4 = (q >> 6) * 4;
            float4 v = *(const float4*)(g_kvlin + kbase + (long long)r*1024 + c4);
            sKV[(c4+0)*64 + r] = v.x;
            sKV[(c4+1)*64 + r] = v.y;
            sKV[(c4+2)*64 + r] = v.z;
            sKV[(c4+3)*64 + r] = v.w;
        }
        __syncthreads();

        float acc[4][4];
        #pragma unroll
        for (int i = 0; i < 4; i++)
            #pragma unroll
            for (int j = 0; j < 4; j++) acc[i][j] = 0.0f;

        #pragma unroll 8
        for (int kk = 0; kk < 64; kk++) {
            float4 av = *(const float4*)&sQT[kk*64 + ty*4];
            float4 bv = *(const float4*)&sKV[kk*64 + tx*4];
            float a[4] = {av.x, av.y, av.z, av.w};
            float bb[4] = {bv.x, bv.y, bv.z, bv.w};
            #pragma unroll
            for (int i = 0; i < 4; i++)
                #pragma unroll
                for (int j = 0; j < 4; j++)
                    acc[i][j] += a[i] * bb[j];
        }

        const int qg = qt*64 + ty*4;
        const float* brow = g_bias + (long long)h*65536;
        #pragma unroll
        for (int i = 0; i < 4; i++) {
            float4 bv = *(const float4*)&brow[(long long)(qg+i)*256 + kt*64 + tx*4];
            float4 o;
            o.x = acc[i][0]*0.125f + bv.x;
            o.y = acc[i][1]*0.125f + bv.y;
            o.z = acc[i][2]*0.125f + bv.z;
            o.w = acc[i][3]*0.125f + bv.w;
            *(float4*)&sS[(ty*4+i)*256 + kt*64 + tx*4] = o;
        }
    }
    __syncthreads();

    // Phase 2: exact softmax over 256-wide rows
    {
        const int wid  = tid >> 5;
        const int lane = tid & 31;
        #pragma unroll
        for (int rr = 0; rr < 8; rr++) {
            float* p = sS + (wid*8 + rr)*256;
            float v[8];
            float mx = -1e30f;
            #pragma unroll
            for (int i = 0; i < 8; i++) {
                v[i] = p[lane + 32*i];
                mx = fmaxf(mx, v[i]);
            }
            #pragma unroll
            for (int off = 16; off > 0; off >>= 1)
                mx = fmaxf(mx, __shfl_xor_sync(0xffffffffu, mx, off));
            float s = 0.0f;
            #pragma unroll
            for (int i = 0; i < 8; i++) {
                v[i] = __expf(v[i] - mx);
                s += v[i];
            }
            #pragma unroll
            for (int off = 16; off > 0; off >>= 1)
                s += __shfl_xor_sync(0xffffffffu, s, off);
            float inv = 1.0f / s;
            #pragma unroll
            for (int i = 0; i < 8; i++)
                p[lane + 32*i] = v[i] * inv;
        }
    }
    __syncthreads();

    // Phase 3: O = P @ V
    float oacc[4][4];
    #pragma unroll
    for (int i = 0; i < 4; i++)
        #pragma unroll
        for (int j = 0; j < 4; j++) oacc[i][j] = 0.0f;

    for (int kt = 0; kt < 4; kt++) {
        const long long vbase = kvb + (long long)(kt*64)*1024 + 512;
        #pragma unroll
        for (int q = tid; q < 1024; q += 256) {
            int r  = q >> 4;
            int c4 = (q & 15) * 4;
            *(float4*)&sKV[r*64 + c4] =
                *(const float4*)(g_kvlin + vbase + (long long)r*1024 + c4);
        }
        __syncthreads();

        #pragma unroll 8
        for (int kl = 0; kl < 64; kl++) {
            float4 bv = *(const float4*)&sKV[kl*64 + tx*4];
            float bb[4] = {bv.x, bv.y, bv.z, bv.w};
            float a[4];
            #pragma unroll
            for (int i = 0; i < 4; i++)
                a[i] = sS[(ty*4+i)*256 + kt*64 + kl];
            #pragma unroll
            for (int i = 0; i < 4; i++)
                #pragma unroll
                for (int j = 0; j < 4; j++)
                    oacc[i][j] += a[i] * bb[j];
        }
        __syncthreads();
    }

    const long long obase = (long long)b*131072 + (long long)(qt*64)*512 + h*64;
    #pragma unroll
    for (int i = 0; i < 4; i++) {
        float4 o;
        o.x = oacc[i][0]; o.y = oacc[i][1];
        o.z = oacc[i][2]; o.w = oacc[i][3];
        *(float4*)(g_o + obase + (long long)(ty*4+i)*512 + tx*4) = o;
    }
}

// ---------------------------------------------------------------------------
// Relative-position bias matrix g_bias[h][i][j] from bias_table [961,8].
// ---------------------------------------------------------------------------
__global__ void __launch_bounds__(256)
k_build_bias(const float* __restrict__ table)
{
    int t = blockIdx.x * blockDim.x + threadIdx.x;   // 65536 = 256*256
    int i = t >> 8, j = t & 255;
    int dh = (i >> 4) - (j >> 4) + 15;
    int dw = (i & 15) - (j & 15) + 15;
    int idx = dh * 31 + dw;                          // 2*16-1 = 31
    #pragma unroll
    for (int h = 0; h < 8; h++)
        g_bias[(long long)h * 65536 + t] = table[idx * 8 + h];
}

// ---------------------------------------------------------------------------
extern "C" void kernel_launch(void* const* d_in, const int* in_sizes, int n_in,
                              void* d_out, int out_size)
{
    const float* x      = (const float*)d_in[0];  // [128,256,512]
    const float* y      = (const float*)d_in[1];  // [128,256,512]
    const float* q_w    = (const float*)d_in[2];  // [512,512]
    const float* kv_w   = (const float*)d_in[3];  // [512,1024]
    const float* proj_w = (const float*)d_in[4];  // [512,512]
    const float* proj_b = (const float*)d_in[5];  // [512]
    const float* table  = (const float*)d_in[6];  // [961,8]
    float* out = (float*)d_out;

    cudaFuncSetAttribute(k_attn_fused,
                         cudaFuncAttributeMaxDynamicSharedMemorySize, 98304);

    k_build_bias<<<256, 256>>>(table);

    k_gemm_q <<<dim3(512/128,  32768/128, 1), 256>>>(x, q_w);
    k_gemm_kv<<<dim3(1024/128, 32768/128, 1), 256>>>(y, kv_w);

    k_attn_fused<<<dim3(4, 8, 128), 256, 98304>>>();

    k_gemm_proj<<<dim3(512/128, 32768/128, 1), 256>>>(proj_w, proj_b, out);
}

// round 9
// speedup vs baseline: 2.9222x; 1.4522x over previous
#include <cuda_runtime.h>
#include <cuda_bf16.h>
#include <math.h>
#include <stdint.h>

// Swin-style window cross-attention.
// B=128, N=256 (16x16 window), C=512, H=8, d=64.

// Scratch (device globals; no allocation anywhere).
__device__ float g_qlin [32768LL * 512];   // [B*N, C]      64 MB
__device__ float g_kvlin[32768LL * 1024];  // [B*N, 2C]    128 MB
__device__ float g_o    [32768LL * 512];   // [B,N,C]       64 MB (head-interleaved)
__device__ float g_bias [8LL * 256 * 256]; // [H,N,N]        2 MB

// ---------------------------------------------------------------------------
// Helpers
// ---------------------------------------------------------------------------
__device__ __forceinline__ uint32_t smem_u32(const void* p) {
    return (uint32_t)__cvta_generic_to_shared(p);
}
__device__ __forceinline__ uint32_t pack_bf2(float a, float b) {
    __nv_bfloat162 t = __floats2bfloat162_rn(a, b);
    return *reinterpret_cast<uint32_t*>(&t);
}
__device__ __forceinline__ void ldm_x4(uint32_t* r, uint32_t addr) {
    asm volatile("ldmatrix.sync.aligned.m8n8.x4.shared.b16 {%0,%1,%2,%3}, [%4];"
                 : "=r"(r[0]), "=r"(r[1]), "=r"(r[2]), "=r"(r[3]) : "r"(addr));
}
__device__ __forceinline__ void ldm_x4_t(uint32_t* r, uint32_t addr) {
    asm volatile("ldmatrix.sync.aligned.m8n8.x4.trans.shared.b16 {%0,%1,%2,%3}, [%4];"
                 : "=r"(r[0]), "=r"(r[1]), "=r"(r[2]), "=r"(r[3]) : "r"(addr));
}
__device__ __forceinline__ void mma_bf16(float* c, const uint32_t* a, const uint32_t* b) {
    asm volatile(
        "mma.sync.aligned.m16n8k16.row.col.f32.bf16.bf16.f32 "
        "{%0,%1,%2,%3}, {%4,%5,%6,%7}, {%8,%9}, {%0,%1,%2,%3};"
        : "+f"(c[0]), "+f"(c[1]), "+f"(c[2]), "+f"(c[3])
        : "r"(a[0]), "r"(a[1]), "r"(a[2]), "r"(a[3]), "r"(b[0]), "r"(b[1]));
}

// ---------------------------------------------------------------------------
// Split-bf16 tensor-core GEMM: C[M,N] = A[M,K] @ B[K,N] (+ optional col bias).
// CTA tile 128x128, BK=32, 256 threads, 8 warps (4m x 2n), warp 32x64.
// ---------------------------------------------------------------------------
template<int EPI, int M, int N, int K, int LDA, int LDB, int LDC>
__device__ __forceinline__ void
mma_gemm_body(const float* __restrict__ A, const float* __restrict__ Bm,
              float* __restrict__ C, const float* __restrict__ bias)
{
    constexpr int BK  = 32;
    constexpr int PA  = 40;
    constexpr int PB  = 136;

    __shared__ __nv_bfloat16 sAh[128 * PA];
    __shared__ __nv_bfloat16 sAl[128 * PA];
    __shared__ __nv_bfloat16 sBh[BK * PB];
    __shared__ __nv_bfloat16 sBl[BK * PB];

    const int tid  = threadIdx.x;
    const int wid  = tid >> 5;
    const int lane = tid & 31;
    const int wm   = wid >> 1;
    const int wn   = wid & 1;
    const int row0 = blockIdx.y * 128;
    const int col0 = blockIdx.x * 128;

    float acc[2][8][4];
    #pragma unroll
    for (int i = 0; i < 2; i++)
        #pragma unroll
        for (int j = 0; j < 8; j++)
            #pragma unroll
            for (int q = 0; q < 4; q++) acc[i][j][q] = 0.0f;

    const int ar  = tid >> 3;
    const int ac4 = (tid & 7) * 4;
    const int br  = tid >> 5;
    const int bc4 = (tid & 31) * 4;

    for (int k0 = 0; k0 < K; k0 += BK) {
        #pragma unroll
        for (int i = 0; i < 4; i++) {
            int r = ar + i * 32;
            float4 v = *(const float4*)(A + (long long)(row0 + r) * LDA + k0 + ac4);
            float h0 = __bfloat162float(__float2bfloat16_rn(v.x));
            float h1 = __bfloat162float(__float2bfloat16_rn(v.y));
            float h2 = __bfloat162float(__float2bfloat16_rn(v.z));
            float h3 = __bfloat162float(__float2bfloat16_rn(v.w));
            uint2 ph = { pack_bf2(h0, h1), pack_bf2(h2, h3) };
            uint2 pl = { pack_bf2(v.x - h0, v.y - h1), pack_bf2(v.z - h2, v.w - h3) };
            *(uint2*)&sAh[r * PA + ac4] = ph;
            *(uint2*)&sAl[r * PA + ac4] = pl;
        }
        #pragma unroll
        for (int i = 0; i < 4; i++) {
            int r = br + i * 8;
            float4 v = *(const float4*)(Bm + (long long)(k0 + r) * LDB + col0 + bc4);
            float h0 = __bfloat162float(__float2bfloat16_rn(v.x));
            float h1 = __bfloat162float(__float2bfloat16_rn(v.y));
            float h2 = __bfloat162float(__float2bfloat16_rn(v.z));
            float h3 = __bfloat162float(__float2bfloat16_rn(v.w));
            uint2 ph = { pack_bf2(h0, h1), pack_bf2(h2, h3) };
            uint2 pl = { pack_bf2(v.x - h0, v.y - h1), pack_bf2(v.z - h2, v.w - h3) };
            *(uint2*)&sBh[r * PB + bc4] = ph;
            *(uint2*)&sBl[r * PB + bc4] = pl;
        }
        __syncthreads();

        #pragma unroll
        for (int ks = 0; ks < 2; ks++) {
            const int arow = wm * 32 + (lane & 15);
            const int acol = ks * 16 + ((lane >> 4) << 3);
            const int brow = ks * 16 + (lane & 15);

            uint32_t ah[2][4], al[2][4], bb[8][2];

            #pragma unroll
            for (int mf = 0; mf < 2; mf++)
                ldm_x4(ah[mf], smem_u32(&sAh[(arow + mf * 16) * PA + acol]));
            #pragma unroll
            for (int np = 0; np < 4; np++) {
                uint32_t r[4];
                int bcol = wn * 64 + np * 16 + ((lane >> 4) << 3);
                ldm_x4_t(r, smem_u32(&sBh[brow * PB + bcol]));
                bb[2*np][0] = r[0]; bb[2*np][1] = r[1];
                bb[2*np+1][0] = r[2]; bb[2*np+1][1] = r[3];
            }
            #pragma unroll
            for (int mf = 0; mf < 2; mf++)
                #pragma unroll
                for (int nf = 0; nf < 8; nf++)
                    mma_bf16(acc[mf][nf], ah[mf], bb[nf]);

            #pragma unroll
            for (int mf = 0; mf < 2; mf++)
                ldm_x4(al[mf], smem_u32(&sAl[(arow + mf * 16) * PA + acol]));
            #pragma unroll
            for (int mf = 0; mf < 2; mf++)
                #pragma unroll
                for (int nf = 0; nf < 8; nf++)
                    mma_bf16(acc[mf][nf], al[mf], bb[nf]);

            #pragma unroll
            for (int np = 0; np < 4; np++) {
                uint32_t r[4];
                int bcol = wn * 64 + np * 16 + ((lane >> 4) << 3);
                ldm_x4_t(r, smem_u32(&sBl[brow * PB + bcol]));
                bb[2*np][0] = r[0]; bb[2*np][1] = r[1];
                bb[2*np+1][0] = r[2]; bb[2*np+1][1] = r[3];
            }
            #pragma unroll
            for (int mf = 0; mf < 2; mf++)
                #pragma unroll
                for (int nf = 0; nf < 8; nf++)
                    mma_bf16(acc[mf][nf], ah[mf], bb[nf]);
        }
        __syncthreads();
    }

    #pragma unroll
    for (int mf = 0; mf < 2; mf++) {
        #pragma unroll
        for (int nf = 0; nf < 8; nf++) {
            int r = row0 + wm * 32 + mf * 16 + (lane >> 2);
            int c = col0 + wn * 64 + nf * 8 + (lane & 3) * 2;
            float2 v0 = { acc[mf][nf][0], acc[mf][nf][1] };
            float2 v1 = { acc[mf][nf][2], acc[mf][nf][3] };
            if (EPI == 1) {
                v0.x += bias[c]; v0.y += bias[c + 1];
                v1.x += bias[c]; v1.y += bias[c + 1];
            }
            *(float2*)(C + (long long)r * LDC + c)       = v0;
            *(float2*)(C + (long long)(r + 8) * LDC + c) = v1;
        }
    }
}

__global__ void __launch_bounds__(256)
k_gemm_q(const float* __restrict__ x, const float* __restrict__ q_w)
{
    mma_gemm_body<0, 32768,512,512, 512,512,512>(x, q_w, g_qlin, nullptr);
}

__global__ void __launch_bounds__(256)
k_gemm_kv(const float* __restrict__ y, const float* __restrict__ kv_w)
{
    mma_gemm_body<0, 32768,1024,512, 512,1024,1024>(y, kv_w, g_kvlin, nullptr);
}

__global__ void __launch_bounds__(256)
k_gemm_proj(const float* __restrict__ proj_w, const float* __restrict__ proj_b,
            float* __restrict__ out)
{
    mma_gemm_body<1, 32768,512,512, 512,512,512>(g_o, proj_w, out, proj_b);
}

// ---------------------------------------------------------------------------
// Fused attention, tensor-core version.
// CTA = (q-tile 64, head, batch); 128 threads = 4 warps; warp owns 16 q-rows
// and the full 256-wide score stripe (softmax entirely in registers).
//   S = (0.125*Q) K^T (3-term split) + bias; softmax; O = P V (3-term split).
// smem (dynamic, 90KB): Qh/Ql [64][72] bf16, KVh/KVl [256][72] bf16
// (KV region holds K during phase 1, V during phase 2).
// ---------------------------------------------------------------------------
__global__ void __launch_bounds__(128)
k_attn_fused()
{
    constexpr int PQ = 72;   // pitches: 144B stride ≡ 16 mod 128 -> conflict-free
    constexpr int PK = 72;

    extern __shared__ __nv_bfloat16 smb[];
    __nv_bfloat16* sQh = smb;                 //  4608 elems
    __nv_bfloat16* sQl = smb + 4608;
    __nv_bfloat16* sKh = smb + 9216;          // 18432 elems
    __nv_bfloat16* sKl = smb + 27648;

    const int tid  = threadIdx.x;
    const int wid  = tid >> 5;         // 0..3 -> q rows [wid*16, wid*16+16)
    const int lane = tid & 31;
    const int qt   = blockIdx.x;
    const int h    = blockIdx.y;
    const int b    = blockIdx.z;

    const long long qbase = (long long)b*131072 + (long long)(qt*64)*512 + h*64;
    const long long kvb   = (long long)b*262144 + h*64;

    // ---- stage Q (scaled by 0.125, split hi/lo) : [64][64]
    #pragma unroll
    for (int i = 0; i < 8; i++) {
        int f  = i * 128 + tid;            // 1024 float4s
        int r  = f >> 4;
        int c4 = (f & 15) * 4;
        float4 v = *(const float4*)(g_qlin + qbase + (long long)r*512 + c4);
        v.x *= 0.125f; v.y *= 0.125f; v.z *= 0.125f; v.w *= 0.125f;
        float h0 = __bfloat162float(__float2bfloat16_rn(v.x));
        float h1 = __bfloat162float(__float2bfloat16_rn(v.y));
        float h2 = __bfloat162float(__float2bfloat16_rn(v.z));
        float h3 = __bfloat162float(__float2bfloat16_rn(v.w));
        uint2 ph = { pack_bf2(h0, h1), pack_bf2(h2, h3) };
        uint2 pl = { pack_bf2(v.x - h0, v.y - h1), pack_bf2(v.z - h2, v.w - h3) };
        *(uint2*)&sQh[r * PQ + c4] = ph;
        *(uint2*)&sQl[r * PQ + c4] = pl;
    }
    // ---- stage K (split hi/lo): [256 tokens][64 dims], row-major copy
    #pragma unroll
    for (int i = 0; i < 32; i++) {
        int f  = i * 128 + tid;            // 4096 float4s
        int r  = f >> 4;
        int c4 = (f & 15) * 4;
        float4 v = *(const float4*)(g_kvlin + kvb + (long long)r*1024 + c4);
        float h0 = __bfloat162float(__float2bfloat16_rn(v.x));
        float h1 = __bfloat162float(__float2bfloat16_rn(v.y));
        float h2 = __bfloat162float(__float2bfloat16_rn(v.z));
        float h3 = __bfloat162float(__float2bfloat16_rn(v.w));
        uint2 ph = { pack_bf2(h0, h1), pack_bf2(h2, h3) };
        uint2 pl = { pack_bf2(v.x - h0, v.y - h1), pack_bf2(v.z - h2, v.w - h3) };
        *(uint2*)&sKh[r * PK + c4] = ph;
        *(uint2*)&sKl[r * PK + c4] = pl;
    }
    __syncthreads();

    // ---- Phase 1: S = Q' K^T  (32 n-frags x 4 accs per lane)
    float acc[32][4];
    #pragma unroll
    for (int nf = 0; nf < 32; nf++)
        #pragma unroll
        for (int q = 0; q < 4; q++) acc[nf][q] = 0.0f;

    #pragma unroll
    for (int s = 0; s < 4; s++) {            // k16 steps over d=64
        const int arow = wid * 16 + (lane & 15);
        const int acol = s * 16 + ((lane >> 4) << 3);
        uint32_t ah[4], al[4];
        ldm_x4(ah, smem_u32(&sQh[arow * PQ + acol]));
        ldm_x4(al, smem_u32(&sQl[arow * PQ + acol]));

        // B operand from [n][k] row-major K: non-trans ldmatrix
        const int brow_base = (lane & 7) + ((lane >> 4) << 3);
        const int bcol      = s * 16 + (((lane >> 3) & 1) << 3);
        #pragma unroll
        for (int np = 0; np < 16; np++) {
            uint32_t rh[4];
            ldm_x4(rh, smem_u32(&sKh[(np*16 + brow_base) * PK + bcol]));
            uint32_t b0[2] = { rh[0], rh[1] };
            uint32_t b1[2] = { rh[2], rh[3] };
            mma_bf16(acc[2*np],   ah, b0);
            mma_bf16(acc[2*np+1], ah, b1);
            mma_bf16(acc[2*np],   al, b0);
            mma_bf16(acc[2*np+1], al, b1);
            uint32_t rl[4];
            ldm_x4(rl, smem_u32(&sKl[(np*16 + brow_base) * PK + bcol]));
            uint32_t c0[2] = { rl[0], rl[1] };
            uint32_t c1[2] = { rl[2], rl[3] };
            mma_bf16(acc[2*np],   ah, c0);
            mma_bf16(acc[2*np+1], ah, c1);
        }
    }

    // ---- add relative-position bias (gmem, L2-resident)
    {
        const int r0 = qt*64 + wid*16 + (lane >> 2);
        const float* br0 = g_bias + (long long)h*65536 + (long long)r0*256;
        const float* br8 = br0 + 8*256;
        const int cb = (lane & 3) * 2;
        #pragma unroll
        for (int nf = 0; nf < 32; nf++) {
            float2 b0 = *(const float2*)&br0[nf*8 + cb];
            float2 b8 = *(const float2*)&br8[nf*8 + cb];
            acc[nf][0] += b0.x; acc[nf][1] += b0.y;
            acc[nf][2] += b8.x; acc[nf][3] += b8.y;
        }
    }

    // ---- V staging can start as soon as all warps stop reading K
    __syncthreads();
    // (stage V below after softmax bookkeeping interleave — do it now to
    //  overlap store latency with the register softmax)
    // ---- Phase 2: softmax in registers (rows r0 = c0/c1, r0+8 = c2/c3)
    float mx0 = -1e30f, mx1 = -1e30f;
    #pragma unroll
    for (int nf = 0; nf < 32; nf++) {
        mx0 = fmaxf(mx0, fmaxf(acc[nf][0], acc[nf][1]));
        mx1 = fmaxf(mx1, fmaxf(acc[nf][2], acc[nf][3]));
    }
    mx0 = fmaxf(mx0, __shfl_xor_sync(0xffffffffu, mx0, 1));
    mx0 = fmaxf(mx0, __shfl_xor_sync(0xffffffffu, mx0, 2));
    mx1 = fmaxf(mx1, __shfl_xor_sync(0xffffffffu, mx1, 1));
    mx1 = fmaxf(mx1, __shfl_xor_sync(0xffffffffu, mx1, 2));

    float s0 = 0.0f, s1 = 0.0f;
    #pragma unroll
    for (int nf = 0; nf < 32; nf++) {
        acc[nf][0] = __expf(acc[nf][0] - mx0);
        acc[nf][1] = __expf(acc[nf][1] - mx0);
        acc[nf][2] = __expf(acc[nf][2] - mx1);
        acc[nf][3] = __expf(acc[nf][3] - mx1);
        s0 += acc[nf][0] + acc[nf][1];
        s1 += acc[nf][2] + acc[nf][3];
    }
    s0 += __shfl_xor_sync(0xffffffffu, s0, 1);
    s0 += __shfl_xor_sync(0xffffffffu, s0, 2);
    s1 += __shfl_xor_sync(0xffffffffu, s1, 1);
    s1 += __shfl_xor_sync(0xffffffffu, s1, 2);
    const float inv0 = 1.0f / s0;
    const float inv1 = 1.0f / s1;

    // convert P to hi/lo bf16 pairs (packed along k)
    uint32_t pH[32], pH8[32], pL[32], pL8[32];
    #pragma unroll
    for (int nf = 0; nf < 32; nf++) {
        float p0 = acc[nf][0]*inv0, p1 = acc[nf][1]*inv0;
        float p2 = acc[nf][2]*inv1, p3 = acc[nf][3]*inv1;
        float h0 = __bfloat162float(__float2bfloat16_rn(p0));
        float h1 = __bfloat162float(__float2bfloat16_rn(p1));
        float h2 = __bfloat162float(__float2bfloat16_rn(p2));
        float h3 = __bfloat162float(__float2bfloat16_rn(p3));
        pH [nf] = pack_bf2(h0, h1);
        pH8[nf] = pack_bf2(h2, h3);
        pL [nf] = pack_bf2(p0 - h0, p1 - h1);
        pL8[nf] = pack_bf2(p2 - h2, p3 - h3);
    }

    // ---- stage V (overwrites K region): [256 tokens][64 dims]
    #pragma unroll
    for (int i = 0; i < 32; i++) {
        int f  = i * 128 + tid;
        int r  = f >> 4;
        int c4 = (f & 15) * 4;
        float4 v = *(const float4*)(g_kvlin + kvb + 512 + (long long)r*1024 + c4);
        float h0 = __bfloat162float(__float2bfloat16_rn(v.x));
        float h1 = __bfloat162float(__float2bfloat16_rn(v.y));
        float h2 = __bfloat162float(__float2bfloat16_rn(v.z));
        float h3 = __bfloat162float(__float2bfloat16_rn(v.w));
        uint2 ph = { pack_bf2(h0, h1), pack_bf2(h2, h3) };
        uint2 pl = { pack_bf2(v.x - h0, v.y - h1), pack_bf2(v.z - h2, v.w - h3) };
        *(uint2*)&sKh[r * PK + c4] = ph;
        *(uint2*)&sKl[r * PK + c4] = pl;
    }
    __syncthreads();

    // ---- Phase 3: O = P V   (k = 256 tokens, n = 64 dims)
    float oacc[8][4];
    #pragma unroll
    for (int nf = 0; nf < 8; nf++)
        #pragma unroll
        for (int q = 0; q < 4; q++) oacc[nf][q] = 0.0f;

    #pragma unroll
    for (int s = 0; s < 16; s++) {           // k16 steps over 256 tokens
        uint32_t ah[4] = { pH[2*s], pH8[2*s], pH[2*s+1], pH8[2*s+1] };
        uint32_t al[4] = { pL[2*s], pL8[2*s], pL[2*s+1], pL8[2*s+1] };
        const int brow = s * 16 + (lane & 15);
        #pragma unroll
        for (int np = 0; np < 4; np++) {
            int bcol = np * 16 + ((lane >> 4) << 3);
            uint32_t rh[4];
            ldm_x4_t(rh, smem_u32(&sKh[brow * PK + bcol]));
            uint32_t b0[2] = { rh[0], rh[1] };
            uint32_t b1[2] = { rh[2], rh[3] };
            mma_bf16(oacc[2*np],   ah, b0);
            mma_bf16(oacc[2*np+1], ah, b1);
            mma_bf16(oacc[2*np],   al, b0);
            mma_bf16(oacc[2*np+1], al, b1);
            uint32_t rl[4];
            ldm_x4_t(rl, smem_u32(&sKl[brow * PK + bcol]));
            uint32_t c0[2] = { rl[0], rl[1] };
            uint32_t c1[2] = { rl[2], rl[3] };
            mma_bf16(oacc[2*np],   ah, c0);
            mma_bf16(oacc[2*np+1], ah, c1);
        }
    }

    // ---- epilogue: write O head-interleaved
    const long long obase = (long long)b*131072 + (long long)(qt*64)*512 + h*64;
    {
        const int r0 = wid*16 + (lane >> 2);
        const int cb = (lane & 3) * 2;
        #pragma unroll
        for (int nf = 0; nf < 8; nf++) {
            float2 v0 = { oacc[nf][0], oacc[nf][1] };
            float2 v1 = { oacc[nf][2], oacc[nf][3] };
            *(float2*)(g_o + obase + (long long)r0*512     + nf*8 + cb) = v0;
            *(float2*)(g_o + obase + (long long)(r0+8)*512 + nf*8 + cb) = v1;
        }
    }
}

// ---------------------------------------------------------------------------
// Relative-position bias matrix g_bias[h][i][j] from bias_table [961,8].
// ---------------------------------------------------------------------------
__global__ void __launch_bounds__(256)
k_build_bias(const float* __restrict__ table)
{
    int t = blockIdx.x * blockDim.x + threadIdx.x;   // 65536 = 256*256
    int i = t >> 8, j = t & 255;
    int dh = (i >> 4) - (j >> 4) + 15;
    int dw = (i & 15) - (j & 15) + 15;
    int idx = dh * 31 + dw;
    #pragma unroll
    for (int h = 0; h < 8; h++)
        g_bias[(long long)h * 65536 + t] = table[idx * 8 + h];
}

// ---------------------------------------------------------------------------
extern "C" void kernel_launch(void* const* d_in, const int* in_sizes, int n_in,
                              void* d_out, int out_size)
{
    const float* x      = (const float*)d_in[0];
    const float* y      = (const float*)d_in[1];
    const float* q_w    = (const float*)d_in[2];
    const float* kv_w   = (const float*)d_in[3];
    const float* proj_w = (const float*)d_in[4];
    const float* proj_b = (const float*)d_in[5];
    const float* table  = (const float*)d_in[6];
    float* out = (float*)d_out;

    cudaFuncSetAttribute(k_attn_fused,
                         cudaFuncAttributeMaxDynamicSharedMemorySize, 92160);

    k_build_bias<<<256, 256>>>(table);

    k_gemm_q <<<dim3(512/128,  32768/128, 1), 256>>>(x, q_w);
    k_gemm_kv<<<dim3(1024/128, 32768/128, 1), 256>>>(y, kv_w);

    k_attn_fused<<<dim3(4, 8, 128), 128, 92160>>>();

    k_gemm_proj<<<dim3(512/128, 32768/128, 1), 256>>>(proj_w, proj_b, out);
}